// round 4
// baseline (speedup 1.0000x reference)
#include <cuda_runtime.h>
#include <cstdint>

#define NU 100000
#define NI 50000
#define CH 128
#define NE 600000
#define NLAY 2

// ---------------- scratch (device globals; no allocation allowed) ------------
__device__ float g_xu[NU * CH];
__device__ float g_xi[NI * CH];
__device__ float g_agg_u[NU * CH];
__device__ float g_agg_i[NI * CH];
__device__ float g_t1u[NU * CH];
__device__ float g_t2u[NU * CH];
__device__ float g_t1i[NI * CH];
__device__ float g_t2i[NI * CH];

// ---------------- packed f32x2 helpers ---------------------------------------
__device__ __forceinline__ unsigned long long pk2(float x, float y) {
    unsigned long long r;
    asm("mov.b64 %0, {%1, %2};" : "=l"(r) : "f"(x), "f"(y));
    return r;
}
__device__ __forceinline__ void fma2(unsigned long long& d, unsigned long long a,
                                     unsigned long long b) {
    asm("fma.rn.f32x2 %0, %1, %2, %0;" : "+l"(d) : "l"(a), "l"(b));
}
__device__ __forceinline__ void upk(unsigned long long v, float& lo, float& hi) {
    asm("mov.b64 {%0, %1}, %2;" : "=f"(lo), "=f"(hi) : "l"(v));
}

// ---------------- GEMM: Y[M,128] = act( (alpha*X + AGG) @ W + bias ) ---------
// BM=BN=128, BK=32, 256 threads, 8x8 register tile, f32x2 packed FMA.
__global__ __launch_bounds__(256) void gemm128(
    const float* __restrict__ X, const float* __restrict__ AGG,
    const float* __restrict__ epsp, const float* __restrict__ W,
    const float* __restrict__ bias, float* __restrict__ Y, int M, int do_relu) {
    __shared__ float As[128][32];
    __shared__ float Bs[32][128];

    const int tid = threadIdx.x;
    const int tx = tid & 15;          // 0..15 -> col tile
    const int ty = tid >> 4;          // 0..15 -> row tile
    const int row0 = blockIdx.x * 128 + ty * 8;

    float alpha = 1.0f;
    if (epsp) alpha = 1.0f + __ldg(epsp);

    unsigned long long acc[8][4];
#pragma unroll
    for (int i = 0; i < 8; i++)
#pragma unroll
        for (int j = 0; j < 4; j++) acc[i][j] = 0ULL;

#pragma unroll 1
    for (int kc = 0; kc < 128; kc += 32) {
        // load A tile (with fused (1+eps)*x + agg), rows of this m-tile
#pragma unroll
        for (int q = 0; q < 4; q++) {
            int f = tid + 256 * q;
            int r = f >> 3, c4 = f & 7;
            int grow = blockIdx.x * 128 + r;
            float4 v = make_float4(0.f, 0.f, 0.f, 0.f);
            if (grow < M) {
                v = *(const float4*)(X + (size_t)grow * CH + kc + c4 * 4);
                if (AGG) {
                    const float4 g =
                        *(const float4*)(AGG + (size_t)grow * CH + kc + c4 * 4);
                    v.x = fmaf(alpha, v.x, g.x);
                    v.y = fmaf(alpha, v.y, g.y);
                    v.z = fmaf(alpha, v.z, g.z);
                    v.w = fmaf(alpha, v.w, g.w);
                }
            }
            *(float4*)&As[r][c4 * 4] = v;
        }
        // load B tile (weights, no guard: K=N=128)
#pragma unroll
        for (int q = 0; q < 4; q++) {
            int f = tid + 256 * q;
            int r = f >> 5, c4 = f & 31;
            *(float4*)&Bs[r][c4 * 4] =
                *(const float4*)(W + (size_t)(kc + r) * CH + c4 * 4);
        }
        __syncthreads();

#pragma unroll
        for (int kk = 0; kk < 32; kk++) {
            unsigned long long pa[8];
#pragma unroll
            for (int i = 0; i < 8; i++) {
                float a = As[ty * 8 + i][kk];
                pa[i] = pk2(a, a);
            }
            const ulonglong2 bb0 = *(const ulonglong2*)&Bs[kk][tx * 8];
            const ulonglong2 bb1 = *(const ulonglong2*)&Bs[kk][tx * 8 + 4];
            unsigned long long bq[4] = {bb0.x, bb0.y, bb1.x, bb1.y};
#pragma unroll
            for (int i = 0; i < 8; i++)
#pragma unroll
                for (int j = 0; j < 4; j++) fma2(acc[i][j], pa[i], bq[j]);
        }
        __syncthreads();
    }

    // epilogue: bias (+ relu) + store
    const float4 bv0 = *(const float4*)(bias + tx * 8);
    const float4 bv1 = *(const float4*)(bias + tx * 8 + 4);
    const float bb[8] = {bv0.x, bv0.y, bv0.z, bv0.w, bv1.x, bv1.y, bv1.z, bv1.w};
#pragma unroll
    for (int i = 0; i < 8; i++) {
        int row = row0 + i;
        if (row < M) {
            float y[8];
#pragma unroll
            for (int j = 0; j < 4; j++) upk(acc[i][j], y[2 * j], y[2 * j + 1]);
#pragma unroll
            for (int j = 0; j < 8; j++) {
                y[j] += bb[j];
                if (do_relu) y[j] = fmaxf(y[j], 0.0f);
            }
            float4 o0 = make_float4(y[0], y[1], y[2], y[3]);
            float4 o1 = make_float4(y[4], y[5], y[6], y[7]);
            float* p = Y + (size_t)row * CH + tx * 8;
            *(float4*)p = o0;
            *(float4*)(p + 4) = o1;
        }
    }
}

// ---------------- edge scatter: agg[dst] += x[src], warp per edge ------------
__global__ void edge_scatter(const float* __restrict__ xsrc,
                             const int* __restrict__ esrc,
                             const int* __restrict__ edst,
                             float* __restrict__ agg, int n_edges) {
    int w = (int)((blockIdx.x * (unsigned)blockDim.x + threadIdx.x) >> 5);
    int lane = threadIdx.x & 31;
    if (w >= n_edges) return;
    int s = __ldg(&esrc[w]);
    int d = __ldg(&edst[w]);
    const float4 v = *(const float4*)(xsrc + (size_t)s * CH + lane * 4);
    float* p = agg + (size_t)d * CH + lane * 4;
    asm volatile("red.global.add.v4.f32 [%0], {%1, %2, %3, %4};"
                 :: "l"(p), "f"(v.x), "f"(v.y), "f"(v.z), "f"(v.w)
                 : "memory");
}

// ---------------- LayerNorm (node mode) + ReLU, warp per node ----------------
__global__ void ln_relu(const float* __restrict__ X, const float* __restrict__ g,
                        const float* __restrict__ b, float* __restrict__ Y,
                        int n) {
    int w = (int)((blockIdx.x * (unsigned)blockDim.x + threadIdx.x) >> 5);
    int lane = threadIdx.x & 31;
    if (w >= n) return;
    const float4 v = *(const float4*)(X + (size_t)w * CH + lane * 4);
    float s = v.x + v.y + v.z + v.w;
#pragma unroll
    for (int o = 16; o > 0; o >>= 1) s += __shfl_xor_sync(0xffffffffu, s, o);
    float m = s * (1.0f / CH);
    float dx0 = v.x - m, dx1 = v.y - m, dx2 = v.z - m, dx3 = v.w - m;
    float ss = dx0 * dx0 + dx1 * dx1 + dx2 * dx2 + dx3 * dx3;
#pragma unroll
    for (int o = 16; o > 0; o >>= 1) ss += __shfl_xor_sync(0xffffffffu, ss, o);
    float inv = rsqrtf(ss * (1.0f / CH) + 1e-5f);
    const float4 gv = *(const float4*)(g + lane * 4);
    const float4 bv = *(const float4*)(b + lane * 4);
    float4 o4;
    o4.x = fmaxf(dx0 * inv * gv.x + bv.x, 0.0f);
    o4.y = fmaxf(dx1 * inv * gv.y + bv.y, 0.0f);
    o4.z = fmaxf(dx2 * inv * gv.z + bv.z, 0.0f);
    o4.w = fmaxf(dx3 * inv * gv.w + bv.w, 0.0f);
    *(float4*)(Y + (size_t)w * CH + lane * 4) = o4;
}

// ---------------- orchestration ---------------------------------------------
extern "C" void kernel_launch(void* const* d_in, const int* in_sizes, int n_in,
                              void* d_out, int out_size) {
    const float* x_user = (const float*)d_in[0];
    const float* x_item = (const float*)d_in[1];
    const float* W_init = (const float*)d_in[2];   // (2,128,128)
    const float* b_init = (const float*)d_in[3];   // (2,128)
    const float* mlp_W  = (const float*)d_in[4];   // (L,2,NN,128,128)
    const float* mlp_b  = (const float*)d_in[5];   // (L,2,NN,128)
    const float* eps    = (const float*)d_in[6];   // (L,2)
    const float* ln_g   = (const float*)d_in[7];   // (L,2,128)
    const float* ln_b   = (const float*)d_in[8];   // (L,2,128)
    const int* edge_ui  = (const int*)d_in[9];     // (2,E): [0]=src user, [1]=dst item
    const int* edge_iu  = (const int*)d_in[10];    // (2,E): [0]=src item, [1]=dst user

    float *xu, *xi, *au, *ai, *t1u, *t2u, *t1i, *t2i;
    cudaGetSymbolAddress((void**)&xu, g_xu);
    cudaGetSymbolAddress((void**)&xi, g_xi);
    cudaGetSymbolAddress((void**)&au, g_agg_u);
    cudaGetSymbolAddress((void**)&ai, g_agg_i);
    cudaGetSymbolAddress((void**)&t1u, g_t1u);
    cudaGetSymbolAddress((void**)&t2u, g_t2u);
    cudaGetSymbolAddress((void**)&t1i, g_t1i);
    cudaGetSymbolAddress((void**)&t2i, g_t2i);

    const int gu = (NU + 127) / 128;   // gemm grid users
    const int gi = (NI + 127) / 128;   // gemm grid items
    const int eblk = (NE * 32 + 255) / 256;
    const int lnu = (NU + 7) / 8;
    const int lni = (NI + 7) / 8;

    // init projection (no relu)
    gemm128<<<gu, 256>>>(x_user, nullptr, nullptr, W_init, b_init, xu, NU, 0);
    gemm128<<<gi, 256>>>(x_item, nullptr, nullptr, W_init + 128 * 128,
                         b_init + 128, xi, NI, 0);

    for (int l = 0; l < NLAY; l++) {
        cudaMemsetAsync(ai, 0, (size_t)NI * CH * sizeof(float), 0);
        cudaMemsetAsync(au, 0, (size_t)NU * CH * sizeof(float), 0);
        // user -> item
        edge_scatter<<<eblk, 256>>>(xu, edge_ui, edge_ui + NE, ai, NE);
        // item -> user
        edge_scatter<<<eblk, 256>>>(xi, edge_iu, edge_iu + NE, au, NE);

        // item MLP: edge type 0
        {
            const float* W0 = mlp_W + (size_t)((l * 2 + 0) * 2 + 0) * 128 * 128;
            const float* W1 = mlp_W + (size_t)((l * 2 + 0) * 2 + 1) * 128 * 128;
            const float* B0 = mlp_b + (size_t)((l * 2 + 0) * 2 + 0) * 128;
            const float* B1 = mlp_b + (size_t)((l * 2 + 0) * 2 + 1) * 128;
            gemm128<<<gi, 256>>>(xi, ai, eps + l * 2 + 0, W0, B0, t1i, NI, 1);
            gemm128<<<gi, 256>>>(t1i, nullptr, nullptr, W1, B1, t2i, NI, 1);
        }
        // user MLP: edge type 1
        {
            const float* W0 = mlp_W + (size_t)((l * 2 + 1) * 2 + 0) * 128 * 128;
            const float* W1 = mlp_W + (size_t)((l * 2 + 1) * 2 + 1) * 128 * 128;
            const float* B0 = mlp_b + (size_t)((l * 2 + 1) * 2 + 0) * 128;
            const float* B1 = mlp_b + (size_t)((l * 2 + 1) * 2 + 1) * 128;
            gemm128<<<gu, 256>>>(xu, au, eps + l * 2 + 1, W0, B0, t1u, NU, 1);
            gemm128<<<gu, 256>>>(t1u, nullptr, nullptr, W1, B1, t2u, NU, 1);
        }

        float* ou = (l == NLAY - 1) ? (float*)d_out : xu;
        float* oi = (l == NLAY - 1) ? (float*)d_out + (size_t)NU * CH : xi;
        // node type 0 = user, 1 = item
        ln_relu<<<lnu, 256>>>(t2u, ln_g + (l * 2 + 0) * 128,
                              ln_b + (l * 2 + 0) * 128, ou, NU);
        ln_relu<<<lni, 256>>>(t2i, ln_g + (l * 2 + 1) * 128,
                              ln_b + (l * 2 + 1) * 128, oi, NI);
    }
}

// round 5
// speedup vs baseline: 1.0007x; 1.0007x over previous
#include <cuda_runtime.h>
#include <cstdint>

#define NU 100000
#define NI 50000
#define CH 128
#define NE 600000
#define NLAY 2

// ---------------- scratch (device globals; no allocation allowed) ------------
__device__ float g_xu[NU * CH];
__device__ float g_xi[NI * CH];
__device__ float g_agg_u[NU * CH];
__device__ float g_agg_i[NI * CH];
__device__ float g_t1u[NU * CH];
__device__ float g_t2u[NU * CH];
__device__ float g_t1i[NI * CH];
__device__ float g_t2i[NI * CH];

// ---------------- packed f32x2 helpers ---------------------------------------
__device__ __forceinline__ unsigned long long pk2(float x, float y) {
    unsigned long long r;
    asm("mov.b64 %0, {%1, %2};" : "=l"(r) : "f"(x), "f"(y));
    return r;
}
__device__ __forceinline__ void fma2(unsigned long long& d, unsigned long long a,
                                     unsigned long long b) {
    asm("fma.rn.f32x2 %0, %1, %2, %0;" : "+l"(d) : "l"(a), "l"(b));
}
__device__ __forceinline__ void upk(unsigned long long v, float& lo, float& hi) {
    asm("mov.b64 {%0, %1}, %2;" : "=f"(lo), "=f"(hi) : "l"(v));
}

// ---------------- GEMM: Y[M,128] = act( (alpha*X + AGG) @ W + bias ) ---------
// BM=BN=128, BK=32, 256 threads, 8x8 register tile, f32x2 packed FMA.
__global__ __launch_bounds__(256) void gemm128(
    const float* __restrict__ X, const float* __restrict__ AGG,
    const float* __restrict__ epsp, const float* __restrict__ W,
    const float* __restrict__ bias, float* __restrict__ Y, int M, int do_relu) {
    __shared__ float As[128][32];
    __shared__ float Bs[32][128];

    const int tid = threadIdx.x;
    const int tx = tid & 15;          // 0..15 -> col tile
    const int ty = tid >> 4;          // 0..15 -> row tile
    const int row0 = blockIdx.x * 128 + ty * 8;

    float alpha = 1.0f;
    if (epsp) alpha = 1.0f + __ldg(epsp);

    unsigned long long acc[8][4];
#pragma unroll
    for (int i = 0; i < 8; i++)
#pragma unroll
        for (int j = 0; j < 4; j++) acc[i][j] = 0ULL;

#pragma unroll 1
    for (int kc = 0; kc < 128; kc += 32) {
        // load A tile (with fused (1+eps)*x + agg), rows of this m-tile
#pragma unroll
        for (int q = 0; q < 4; q++) {
            int f = tid + 256 * q;
            int r = f >> 3, c4 = f & 7;
            int grow = blockIdx.x * 128 + r;
            float4 v = make_float4(0.f, 0.f, 0.f, 0.f);
            if (grow < M) {
                v = *(const float4*)(X + (size_t)grow * CH + kc + c4 * 4);
                if (AGG) {
                    const float4 g =
                        *(const float4*)(AGG + (size_t)grow * CH + kc + c4 * 4);
                    v.x = fmaf(alpha, v.x, g.x);
                    v.y = fmaf(alpha, v.y, g.y);
                    v.z = fmaf(alpha, v.z, g.z);
                    v.w = fmaf(alpha, v.w, g.w);
                }
            }
            *(float4*)&As[r][c4 * 4] = v;
        }
        // load B tile (weights, no guard: K=N=128)
#pragma unroll
        for (int q = 0; q < 4; q++) {
            int f = tid + 256 * q;
            int r = f >> 5, c4 = f & 31;
            *(float4*)&Bs[r][c4 * 4] =
                *(const float4*)(W + (size_t)(kc + r) * CH + c4 * 4);
        }
        __syncthreads();

#pragma unroll
        for (int kk = 0; kk < 32; kk++) {
            unsigned long long pa[8];
#pragma unroll
            for (int i = 0; i < 8; i++) {
                float a = As[ty * 8 + i][kk];
                pa[i] = pk2(a, a);
            }
            const ulonglong2 bb0 = *(const ulonglong2*)&Bs[kk][tx * 8];
            const ulonglong2 bb1 = *(const ulonglong2*)&Bs[kk][tx * 8 + 4];
            unsigned long long bq[4] = {bb0.x, bb0.y, bb1.x, bb1.y};
#pragma unroll
            for (int i = 0; i < 8; i++)
#pragma unroll
                for (int j = 0; j < 4; j++) fma2(acc[i][j], pa[i], bq[j]);
        }
        __syncthreads();
    }

    // epilogue: bias (+ relu) + store
    const float4 bv0 = *(const float4*)(bias + tx * 8);
    const float4 bv1 = *(const float4*)(bias + tx * 8 + 4);
    const float bb[8] = {bv0.x, bv0.y, bv0.z, bv0.w, bv1.x, bv1.y, bv1.z, bv1.w};
#pragma unroll
    for (int i = 0; i < 8; i++) {
        int row = row0 + i;
        if (row < M) {
            float y[8];
#pragma unroll
            for (int j = 0; j < 4; j++) upk(acc[i][j], y[2 * j], y[2 * j + 1]);
#pragma unroll
            for (int j = 0; j < 8; j++) {
                y[j] += bb[j];
                if (do_relu) y[j] = fmaxf(y[j], 0.0f);
            }
            float4 o0 = make_float4(y[0], y[1], y[2], y[3]);
            float4 o1 = make_float4(y[4], y[5], y[6], y[7]);
            float* p = Y + (size_t)row * CH + tx * 8;
            *(float4*)p = o0;
            *(float4*)(p + 4) = o1;
        }
    }
}

// ---------------- edge scatter: agg[dst] += x[src], warp per edge ------------
__global__ void edge_scatter(const float* __restrict__ xsrc,
                             const int* __restrict__ esrc,
                             const int* __restrict__ edst,
                             float* __restrict__ agg, int n_edges) {
    int w = (int)((blockIdx.x * (unsigned)blockDim.x + threadIdx.x) >> 5);
    int lane = threadIdx.x & 31;
    if (w >= n_edges) return;
    int s = __ldg(&esrc[w]);
    int d = __ldg(&edst[w]);
    const float4 v = *(const float4*)(xsrc + (size_t)s * CH + lane * 4);
    float* p = agg + (size_t)d * CH + lane * 4;
    asm volatile("red.global.add.v4.f32 [%0], {%1, %2, %3, %4};"
                 :: "l"(p), "f"(v.x), "f"(v.y), "f"(v.z), "f"(v.w)
                 : "memory");
}

// ---------------- LayerNorm (node mode) + ReLU, warp per node ----------------
__global__ void ln_relu(const float* __restrict__ X, const float* __restrict__ g,
                        const float* __restrict__ b, float* __restrict__ Y,
                        int n) {
    int w = (int)((blockIdx.x * (unsigned)blockDim.x + threadIdx.x) >> 5);
    int lane = threadIdx.x & 31;
    if (w >= n) return;
    const float4 v = *(const float4*)(X + (size_t)w * CH + lane * 4);
    float s = v.x + v.y + v.z + v.w;
#pragma unroll
    for (int o = 16; o > 0; o >>= 1) s += __shfl_xor_sync(0xffffffffu, s, o);
    float m = s * (1.0f / CH);
    float dx0 = v.x - m, dx1 = v.y - m, dx2 = v.z - m, dx3 = v.w - m;
    float ss = dx0 * dx0 + dx1 * dx1 + dx2 * dx2 + dx3 * dx3;
#pragma unroll
    for (int o = 16; o > 0; o >>= 1) ss += __shfl_xor_sync(0xffffffffu, ss, o);
    float inv = rsqrtf(ss * (1.0f / CH) + 1e-5f);
    const float4 gv = *(const float4*)(g + lane * 4);
    const float4 bv = *(const float4*)(b + lane * 4);
    float4 o4;
    o4.x = fmaxf(dx0 * inv * gv.x + bv.x, 0.0f);
    o4.y = fmaxf(dx1 * inv * gv.y + bv.y, 0.0f);
    o4.z = fmaxf(dx2 * inv * gv.z + bv.z, 0.0f);
    o4.w = fmaxf(dx3 * inv * gv.w + bv.w, 0.0f);
    *(float4*)(Y + (size_t)w * CH + lane * 4) = o4;
}

// ---------------- orchestration ---------------------------------------------
extern "C" void kernel_launch(void* const* d_in, const int* in_sizes, int n_in,
                              void* d_out, int out_size) {
    const float* x_user = (const float*)d_in[0];
    const float* x_item = (const float*)d_in[1];
    const float* W_init = (const float*)d_in[2];   // (2,128,128)
    const float* b_init = (const float*)d_in[3];   // (2,128)
    const float* mlp_W  = (const float*)d_in[4];   // (L,2,NN,128,128)
    const float* mlp_b  = (const float*)d_in[5];   // (L,2,NN,128)
    const float* eps    = (const float*)d_in[6];   // (L,2)
    const float* ln_g   = (const float*)d_in[7];   // (L,2,128)
    const float* ln_b   = (const float*)d_in[8];   // (L,2,128)
    const int* edge_ui  = (const int*)d_in[9];     // (2,E): [0]=src user, [1]=dst item
    const int* edge_iu  = (const int*)d_in[10];    // (2,E): [0]=src item, [1]=dst user

    float *xu, *xi, *au, *ai, *t1u, *t2u, *t1i, *t2i;
    cudaGetSymbolAddress((void**)&xu, g_xu);
    cudaGetSymbolAddress((void**)&xi, g_xi);
    cudaGetSymbolAddress((void**)&au, g_agg_u);
    cudaGetSymbolAddress((void**)&ai, g_agg_i);
    cudaGetSymbolAddress((void**)&t1u, g_t1u);
    cudaGetSymbolAddress((void**)&t2u, g_t2u);
    cudaGetSymbolAddress((void**)&t1i, g_t1i);
    cudaGetSymbolAddress((void**)&t2i, g_t2i);

    const int gu = (NU + 127) / 128;   // gemm grid users
    const int gi = (NI + 127) / 128;   // gemm grid items
    const int eblk = (NE * 32 + 255) / 256;
    const int lnu = (NU + 7) / 8;
    const int lni = (NI + 7) / 8;

    // init projection (no relu)
    gemm128<<<gu, 256>>>(x_user, nullptr, nullptr, W_init, b_init, xu, NU, 0);
    gemm128<<<gi, 256>>>(x_item, nullptr, nullptr, W_init + 128 * 128,
                         b_init + 128, xi, NI, 0);

    for (int l = 0; l < NLAY; l++) {
        cudaMemsetAsync(ai, 0, (size_t)NI * CH * sizeof(float), 0);
        cudaMemsetAsync(au, 0, (size_t)NU * CH * sizeof(float), 0);
        // user -> item
        edge_scatter<<<eblk, 256>>>(xu, edge_ui, edge_ui + NE, ai, NE);
        // item -> user
        edge_scatter<<<eblk, 256>>>(xi, edge_iu, edge_iu + NE, au, NE);

        // item MLP: edge type 0
        {
            const float* W0 = mlp_W + (size_t)((l * 2 + 0) * 2 + 0) * 128 * 128;
            const float* W1 = mlp_W + (size_t)((l * 2 + 0) * 2 + 1) * 128 * 128;
            const float* B0 = mlp_b + (size_t)((l * 2 + 0) * 2 + 0) * 128;
            const float* B1 = mlp_b + (size_t)((l * 2 + 0) * 2 + 1) * 128;
            gemm128<<<gi, 256>>>(xi, ai, eps + l * 2 + 0, W0, B0, t1i, NI, 1);
            gemm128<<<gi, 256>>>(t1i, nullptr, nullptr, W1, B1, t2i, NI, 1);
        }
        // user MLP: edge type 1
        {
            const float* W0 = mlp_W + (size_t)((l * 2 + 1) * 2 + 0) * 128 * 128;
            const float* W1 = mlp_W + (size_t)((l * 2 + 1) * 2 + 1) * 128 * 128;
            const float* B0 = mlp_b + (size_t)((l * 2 + 1) * 2 + 0) * 128;
            const float* B1 = mlp_b + (size_t)((l * 2 + 1) * 2 + 1) * 128;
            gemm128<<<gu, 256>>>(xu, au, eps + l * 2 + 1, W0, B0, t1u, NU, 1);
            gemm128<<<gu, 256>>>(t1u, nullptr, nullptr, W1, B1, t2u, NU, 1);
        }

        float* ou = (l == NLAY - 1) ? (float*)d_out : xu;
        float* oi = (l == NLAY - 1) ? (float*)d_out + (size_t)NU * CH : xi;
        // node type 0 = user, 1 = item
        ln_relu<<<lnu, 256>>>(t2u, ln_g + (l * 2 + 0) * 128,
                              ln_b + (l * 2 + 0) * 128, ou, NU);
        ln_relu<<<lni, 256>>>(t2i, ln_g + (l * 2 + 1) * 128,
                              ln_b + (l * 2 + 1) * 128, oi, NI);
    }
}

// round 6
// speedup vs baseline: 1.0081x; 1.0073x over previous
#include <cuda_runtime.h>
#include <cstdint>

#define NU 100000
#define NI 50000
#define CH 128
#define NE 600000
#define NLAY 2

// ---------------- scratch (device globals; no allocation allowed) ------------
__device__ float g_xu[NU * CH];
__device__ float g_xi[NI * CH];
__device__ float g_agg_u[NU * CH];
__device__ float g_agg_i[NI * CH];
__device__ float g_t1u[NU * CH];
__device__ float g_t2u[NU * CH];
__device__ float g_t1i[NI * CH];
__device__ float g_t2i[NI * CH];

// ---------------- packed f32x2 helpers ---------------------------------------
__device__ __forceinline__ unsigned long long pk2(float x, float y) {
    unsigned long long r;
    asm("mov.b64 %0, {%1, %2};" : "=l"(r) : "f"(x), "f"(y));
    return r;
}
__device__ __forceinline__ void fma2(unsigned long long& d, unsigned long long a,
                                     unsigned long long b) {
    asm("fma.rn.f32x2 %0, %1, %2, %0;" : "+l"(d) : "l"(a), "l"(b));
}
__device__ __forceinline__ void upk(unsigned long long v, float& lo, float& hi) {
    asm("mov.b64 {%0, %1}, %2;" : "=f"(lo), "=f"(hi) : "l"(v));
}

// ---------------- GEMM: Y[M,128] = act( (alpha*X + AGG) @ W + bias ) ---------
// BM=BN=128, BK=32, 256 threads, 8x8 register tile, f32x2 packed FMA.
__global__ __launch_bounds__(256) void gemm128(
    const float* __restrict__ X, const float* __restrict__ AGG,
    const float* __restrict__ epsp, const float* __restrict__ W,
    const float* __restrict__ bias, float* __restrict__ Y, int M, int do_relu) {
    __shared__ float As[128][32];
    __shared__ float Bs[32][128];

    const int tid = threadIdx.x;
    const int tx = tid & 15;          // 0..15 -> col tile
    const int ty = tid >> 4;          // 0..15 -> row tile
    const int row0 = blockIdx.x * 128 + ty * 8;

    float alpha = 1.0f;
    if (epsp) alpha = 1.0f + __ldg(epsp);

    unsigned long long acc[8][4];
#pragma unroll
    for (int i = 0; i < 8; i++)
#pragma unroll
        for (int j = 0; j < 4; j++) acc[i][j] = 0ULL;

#pragma unroll 1
    for (int kc = 0; kc < 128; kc += 32) {
        // load A tile (with fused (1+eps)*x + agg), rows of this m-tile
#pragma unroll
        for (int q = 0; q < 4; q++) {
            int f = tid + 256 * q;
            int r = f >> 3, c4 = f & 7;
            int grow = blockIdx.x * 128 + r;
            float4 v = make_float4(0.f, 0.f, 0.f, 0.f);
            if (grow < M) {
                v = *(const float4*)(X + (size_t)grow * CH + kc + c4 * 4);
                if (AGG) {
                    const float4 g =
                        *(const float4*)(AGG + (size_t)grow * CH + kc + c4 * 4);
                    v.x = fmaf(alpha, v.x, g.x);
                    v.y = fmaf(alpha, v.y, g.y);
                    v.z = fmaf(alpha, v.z, g.z);
                    v.w = fmaf(alpha, v.w, g.w);
                }
            }
            *(float4*)&As[r][c4 * 4] = v;
        }
        // load B tile (weights, no guard: K=N=128)
#pragma unroll
        for (int q = 0; q < 4; q++) {
            int f = tid + 256 * q;
            int r = f >> 5, c4 = f & 31;
            *(float4*)&Bs[r][c4 * 4] =
                *(const float4*)(W + (size_t)(kc + r) * CH + c4 * 4);
        }
        __syncthreads();

#pragma unroll
        for (int kk = 0; kk < 32; kk++) {
            unsigned long long pa[8];
#pragma unroll
            for (int i = 0; i < 8; i++) {
                float a = As[ty * 8 + i][kk];
                pa[i] = pk2(a, a);
            }
            const ulonglong2 bb0 = *(const ulonglong2*)&Bs[kk][tx * 8];
            const ulonglong2 bb1 = *(const ulonglong2*)&Bs[kk][tx * 8 + 4];
            unsigned long long bq[4] = {bb0.x, bb0.y, bb1.x, bb1.y};
#pragma unroll
            for (int i = 0; i < 8; i++)
#pragma unroll
                for (int j = 0; j < 4; j++) fma2(acc[i][j], pa[i], bq[j]);
        }
        __syncthreads();
    }

    // epilogue: bias (+ relu) + store
    const float4 bv0 = *(const float4*)(bias + tx * 8);
    const float4 bv1 = *(const float4*)(bias + tx * 8 + 4);
    const float bb[8] = {bv0.x, bv0.y, bv0.z, bv0.w, bv1.x, bv1.y, bv1.z, bv1.w};
#pragma unroll
    for (int i = 0; i < 8; i++) {
        int row = row0 + i;
        if (row < M) {
            float y[8];
#pragma unroll
            for (int j = 0; j < 4; j++) upk(acc[i][j], y[2 * j], y[2 * j + 1]);
#pragma unroll
            for (int j = 0; j < 8; j++) {
                y[j] += bb[j];
                if (do_relu) y[j] = fmaxf(y[j], 0.0f);
            }
            float4 o0 = make_float4(y[0], y[1], y[2], y[3]);
            float4 o1 = make_float4(y[4], y[5], y[6], y[7]);
            float* p = Y + (size_t)row * CH + tx * 8;
            *(float4*)p = o0;
            *(float4*)(p + 4) = o1;
        }
    }
}

// ---------------- edge scatter: agg[dst] += x[src], warp per edge ------------
__global__ void edge_scatter(const float* __restrict__ xsrc,
                             const int* __restrict__ esrc,
                             const int* __restrict__ edst,
                             float* __restrict__ agg, int n_edges) {
    int w = (int)((blockIdx.x * (unsigned)blockDim.x + threadIdx.x) >> 5);
    int lane = threadIdx.x & 31;
    if (w >= n_edges) return;
    int s = __ldg(&esrc[w]);
    int d = __ldg(&edst[w]);
    const float4 v = *(const float4*)(xsrc + (size_t)s * CH + lane * 4);
    float* p = agg + (size_t)d * CH + lane * 4;
    asm volatile("red.global.add.v4.f32 [%0], {%1, %2, %3, %4};"
                 :: "l"(p), "f"(v.x), "f"(v.y), "f"(v.z), "f"(v.w)
                 : "memory");
}

// ---------------- LayerNorm (node mode) + ReLU, warp per node ----------------
__global__ void ln_relu(const float* __restrict__ X, const float* __restrict__ g,
                        const float* __restrict__ b, float* __restrict__ Y,
                        int n) {
    int w = (int)((blockIdx.x * (unsigned)blockDim.x + threadIdx.x) >> 5);
    int lane = threadIdx.x & 31;
    if (w >= n) return;
    const float4 v = *(const float4*)(X + (size_t)w * CH + lane * 4);
    float s = v.x + v.y + v.z + v.w;
#pragma unroll
    for (int o = 16; o > 0; o >>= 1) s += __shfl_xor_sync(0xffffffffu, s, o);
    float m = s * (1.0f / CH);
    float dx0 = v.x - m, dx1 = v.y - m, dx2 = v.z - m, dx3 = v.w - m;
    float ss = dx0 * dx0 + dx1 * dx1 + dx2 * dx2 + dx3 * dx3;
#pragma unroll
    for (int o = 16; o > 0; o >>= 1) ss += __shfl_xor_sync(0xffffffffu, ss, o);
    float inv = rsqrtf(ss * (1.0f / CH) + 1e-5f);
    const float4 gv = *(const float4*)(g + lane * 4);
    const float4 bv = *(const float4*)(b + lane * 4);
    float4 o4;
    o4.x = fmaxf(dx0 * inv * gv.x + bv.x, 0.0f);
    o4.y = fmaxf(dx1 * inv * gv.y + bv.y, 0.0f);
    o4.z = fmaxf(dx2 * inv * gv.z + bv.z, 0.0f);
    o4.w = fmaxf(dx3 * inv * gv.w + bv.w, 0.0f);
    *(float4*)(Y + (size_t)w * CH + lane * 4) = o4;
}

// ---------------- orchestration ---------------------------------------------
extern "C" void kernel_launch(void* const* d_in, const int* in_sizes, int n_in,
                              void* d_out, int out_size) {
    const float* x_user = (const float*)d_in[0];
    const float* x_item = (const float*)d_in[1];
    const float* W_init = (const float*)d_in[2];   // (2,128,128)
    const float* b_init = (const float*)d_in[3];   // (2,128)
    const float* mlp_W  = (const float*)d_in[4];   // (L,2,NN,128,128)
    const float* mlp_b  = (const float*)d_in[5];   // (L,2,NN,128)
    const float* eps    = (const float*)d_in[6];   // (L,2)
    const float* ln_g   = (const float*)d_in[7];   // (L,2,128)
    const float* ln_b   = (const float*)d_in[8];   // (L,2,128)
    const int* edge_ui  = (const int*)d_in[9];     // (2,E): [0]=src user, [1]=dst item
    const int* edge_iu  = (const int*)d_in[10];    // (2,E): [0]=src item, [1]=dst user

    float *xu, *xi, *au, *ai, *t1u, *t2u, *t1i, *t2i;
    cudaGetSymbolAddress((void**)&xu, g_xu);
    cudaGetSymbolAddress((void**)&xi, g_xi);
    cudaGetSymbolAddress((void**)&au, g_agg_u);
    cudaGetSymbolAddress((void**)&ai, g_agg_i);
    cudaGetSymbolAddress((void**)&t1u, g_t1u);
    cudaGetSymbolAddress((void**)&t2u, g_t2u);
    cudaGetSymbolAddress((void**)&t1i, g_t1i);
    cudaGetSymbolAddress((void**)&t2i, g_t2i);

    const int gu = (NU + 127) / 128;   // gemm grid users
    const int gi = (NI + 127) / 128;   // gemm grid items
    const int eblk = (NE * 32 + 255) / 256;
    const int lnu = (NU + 7) / 8;
    const int lni = (NI + 7) / 8;

    // init projection (no relu)
    gemm128<<<gu, 256>>>(x_user, nullptr, nullptr, W_init, b_init, xu, NU, 0);
    gemm128<<<gi, 256>>>(x_item, nullptr, nullptr, W_init + 128 * 128,
                         b_init + 128, xi, NI, 0);

    for (int l = 0; l < NLAY; l++) {
        cudaMemsetAsync(ai, 0, (size_t)NI * CH * sizeof(float), 0);
        cudaMemsetAsync(au, 0, (size_t)NU * CH * sizeof(float), 0);
        // user -> item
        edge_scatter<<<eblk, 256>>>(xu, edge_ui, edge_ui + NE, ai, NE);
        // item -> user
        edge_scatter<<<eblk, 256>>>(xi, edge_iu, edge_iu + NE, au, NE);

        // item MLP: edge type 0
        {
            const float* W0 = mlp_W + (size_t)((l * 2 + 0) * 2 + 0) * 128 * 128;
            const float* W1 = mlp_W + (size_t)((l * 2 + 0) * 2 + 1) * 128 * 128;
            const float* B0 = mlp_b + (size_t)((l * 2 + 0) * 2 + 0) * 128;
            const float* B1 = mlp_b + (size_t)((l * 2 + 0) * 2 + 1) * 128;
            gemm128<<<gi, 256>>>(xi, ai, eps + l * 2 + 0, W0, B0, t1i, NI, 1);
            gemm128<<<gi, 256>>>(t1i, nullptr, nullptr, W1, B1, t2i, NI, 1);
        }
        // user MLP: edge type 1
        {
            const float* W0 = mlp_W + (size_t)((l * 2 + 1) * 2 + 0) * 128 * 128;
            const float* W1 = mlp_W + (size_t)((l * 2 + 1) * 2 + 1) * 128 * 128;
            const float* B0 = mlp_b + (size_t)((l * 2 + 1) * 2 + 0) * 128;
            const float* B1 = mlp_b + (size_t)((l * 2 + 1) * 2 + 1) * 128;
            gemm128<<<gu, 256>>>(xu, au, eps + l * 2 + 1, W0, B0, t1u, NU, 1);
            gemm128<<<gu, 256>>>(t1u, nullptr, nullptr, W1, B1, t2u, NU, 1);
        }

        float* ou = (l == NLAY - 1) ? (float*)d_out : xu;
        float* oi = (l == NLAY - 1) ? (float*)d_out + (size_t)NU * CH : xi;
        // node type 0 = user, 1 = item
        ln_relu<<<lnu, 256>>>(t2u, ln_g + (l * 2 + 0) * 128,
                              ln_b + (l * 2 + 0) * 128, ou, NU);
        ln_relu<<<lni, 256>>>(t2i, ln_g + (l * 2 + 1) * 128,
                              ln_b + (l * 2 + 1) * 128, oi, NI);
    }
}

// round 7
// speedup vs baseline: 1.0085x; 1.0005x over previous
#include <cuda_runtime.h>
#include <cstdint>

#define NU 100000
#define NI 50000
#define CH 128
#define NE 600000
#define NLAY 2

// ---------------- scratch (device globals; no allocation allowed) ------------
__device__ float g_xu[NU * CH];
__device__ float g_xi[NI * CH];
__device__ float g_agg_u[NU * CH];
__device__ float g_agg_i[NI * CH];
__device__ float g_t1u[NU * CH];
__device__ float g_t2u[NU * CH];
__device__ float g_t1i[NI * CH];
__device__ float g_t2i[NI * CH];

// ---------------- packed f32x2 helpers ---------------------------------------
__device__ __forceinline__ unsigned long long pk2(float x, float y) {
    unsigned long long r;
    asm("mov.b64 %0, {%1, %2};" : "=l"(r) : "f"(x), "f"(y));
    return r;
}
__device__ __forceinline__ void fma2(unsigned long long& d, unsigned long long a,
                                     unsigned long long b) {
    asm("fma.rn.f32x2 %0, %1, %2, %0;" : "+l"(d) : "l"(a), "l"(b));
}
__device__ __forceinline__ void upk(unsigned long long v, float& lo, float& hi) {
    asm("mov.b64 {%0, %1}, %2;" : "=f"(lo), "=f"(hi) : "l"(v));
}

// ---------------- GEMM: Y[M,128] = act( (alpha*X + AGG) @ W + bias ) ---------
// BM=BN=128, BK=32, 256 threads, 8x8 register tile, f32x2 packed FMA.
__global__ __launch_bounds__(256) void gemm128(
    const float* __restrict__ X, const float* __restrict__ AGG,
    const float* __restrict__ epsp, const float* __restrict__ W,
    const float* __restrict__ bias, float* __restrict__ Y, int M, int do_relu) {
    __shared__ float As[128][32];
    __shared__ float Bs[32][128];

    const int tid = threadIdx.x;
    const int tx = tid & 15;          // 0..15 -> col tile
    const int ty = tid >> 4;          // 0..15 -> row tile
    const int row0 = blockIdx.x * 128 + ty * 8;

    float alpha = 1.0f;
    if (epsp) alpha = 1.0f + __ldg(epsp);

    unsigned long long acc[8][4];
#pragma unroll
    for (int i = 0; i < 8; i++)
#pragma unroll
        for (int j = 0; j < 4; j++) acc[i][j] = 0ULL;

#pragma unroll 1
    for (int kc = 0; kc < 128; kc += 32) {
        // load A tile (with fused (1+eps)*x + agg), rows of this m-tile
#pragma unroll
        for (int q = 0; q < 4; q++) {
            int f = tid + 256 * q;
            int r = f >> 3, c4 = f & 7;
            int grow = blockIdx.x * 128 + r;
            float4 v = make_float4(0.f, 0.f, 0.f, 0.f);
            if (grow < M) {
                v = *(const float4*)(X + (size_t)grow * CH + kc + c4 * 4);
                if (AGG) {
                    const float4 g =
                        *(const float4*)(AGG + (size_t)grow * CH + kc + c4 * 4);
                    v.x = fmaf(alpha, v.x, g.x);
                    v.y = fmaf(alpha, v.y, g.y);
                    v.z = fmaf(alpha, v.z, g.z);
                    v.w = fmaf(alpha, v.w, g.w);
                }
            }
            *(float4*)&As[r][c4 * 4] = v;
        }
        // load B tile (weights, no guard: K=N=128)
#pragma unroll
        for (int q = 0; q < 4; q++) {
            int f = tid + 256 * q;
            int r = f >> 5, c4 = f & 31;
            *(float4*)&Bs[r][c4 * 4] =
                *(const float4*)(W + (size_t)(kc + r) * CH + c4 * 4);
        }
        __syncthreads();

#pragma unroll
        for (int kk = 0; kk < 32; kk++) {
            unsigned long long pa[8];
#pragma unroll
            for (int i = 0; i < 8; i++) {
                float a = As[ty * 8 + i][kk];
                pa[i] = pk2(a, a);
            }
            const ulonglong2 bb0 = *(const ulonglong2*)&Bs[kk][tx * 8];
            const ulonglong2 bb1 = *(const ulonglong2*)&Bs[kk][tx * 8 + 4];
            unsigned long long bq[4] = {bb0.x, bb0.y, bb1.x, bb1.y};
#pragma unroll
            for (int i = 0; i < 8; i++)
#pragma unroll
                for (int j = 0; j < 4; j++) fma2(acc[i][j], pa[i], bq[j]);
        }
        __syncthreads();
    }

    // epilogue: bias (+ relu) + store
    const float4 bv0 = *(const float4*)(bias + tx * 8);
    const float4 bv1 = *(const float4*)(bias + tx * 8 + 4);
    const float bb[8] = {bv0.x, bv0.y, bv0.z, bv0.w, bv1.x, bv1.y, bv1.z, bv1.w};
#pragma unroll
    for (int i = 0; i < 8; i++) {
        int row = row0 + i;
        if (row < M) {
            float y[8];
#pragma unroll
            for (int j = 0; j < 4; j++) upk(acc[i][j], y[2 * j], y[2 * j + 1]);
#pragma unroll
            for (int j = 0; j < 8; j++) {
                y[j] += bb[j];
                if (do_relu) y[j] = fmaxf(y[j], 0.0f);
            }
            float4 o0 = make_float4(y[0], y[1], y[2], y[3]);
            float4 o1 = make_float4(y[4], y[5], y[6], y[7]);
            float* p = Y + (size_t)row * CH + tx * 8;
            *(float4*)p = o0;
            *(float4*)(p + 4) = o1;
        }
    }
}

// ---------------- edge scatter: agg[dst] += x[src], warp per edge ------------
__global__ void edge_scatter(const float* __restrict__ xsrc,
                             const int* __restrict__ esrc,
                             const int* __restrict__ edst,
                             float* __restrict__ agg, int n_edges) {
    int w = (int)((blockIdx.x * (unsigned)blockDim.x + threadIdx.x) >> 5);
    int lane = threadIdx.x & 31;
    if (w >= n_edges) return;
    int s = __ldg(&esrc[w]);
    int d = __ldg(&edst[w]);
    const float4 v = *(const float4*)(xsrc + (size_t)s * CH + lane * 4);
    float* p = agg + (size_t)d * CH + lane * 4;
    asm volatile("red.global.add.v4.f32 [%0], {%1, %2, %3, %4};"
                 :: "l"(p), "f"(v.x), "f"(v.y), "f"(v.z), "f"(v.w)
                 : "memory");
}

// ---------------- LayerNorm (node mode) + ReLU, warp per node ----------------
__global__ void ln_relu(const float* __restrict__ X, const float* __restrict__ g,
                        const float* __restrict__ b, float* __restrict__ Y,
                        int n) {
    int w = (int)((blockIdx.x * (unsigned)blockDim.x + threadIdx.x) >> 5);
    int lane = threadIdx.x & 31;
    if (w >= n) return;
    const float4 v = *(const float4*)(X + (size_t)w * CH + lane * 4);
    float s = v.x + v.y + v.z + v.w;
#pragma unroll
    for (int o = 16; o > 0; o >>= 1) s += __shfl_xor_sync(0xffffffffu, s, o);
    float m = s * (1.0f / CH);
    float dx0 = v.x - m, dx1 = v.y - m, dx2 = v.z - m, dx3 = v.w - m;
    float ss = dx0 * dx0 + dx1 * dx1 + dx2 * dx2 + dx3 * dx3;
#pragma unroll
    for (int o = 16; o > 0; o >>= 1) ss += __shfl_xor_sync(0xffffffffu, ss, o);
    float inv = rsqrtf(ss * (1.0f / CH) + 1e-5f);
    const float4 gv = *(const float4*)(g + lane * 4);
    const float4 bv = *(const float4*)(b + lane * 4);
    float4 o4;
    o4.x = fmaxf(dx0 * inv * gv.x + bv.x, 0.0f);
    o4.y = fmaxf(dx1 * inv * gv.y + bv.y, 0.0f);
    o4.z = fmaxf(dx2 * inv * gv.z + bv.z, 0.0f);
    o4.w = fmaxf(dx3 * inv * gv.w + bv.w, 0.0f);
    *(float4*)(Y + (size_t)w * CH + lane * 4) = o4;
}

// ---------------- orchestration ---------------------------------------------
extern "C" void kernel_launch(void* const* d_in, const int* in_sizes, int n_in,
                              void* d_out, int out_size) {
    const float* x_user = (const float*)d_in[0];
    const float* x_item = (const float*)d_in[1];
    const float* W_init = (const float*)d_in[2];   // (2,128,128)
    const float* b_init = (const float*)d_in[3];   // (2,128)
    const float* mlp_W  = (const float*)d_in[4];   // (L,2,NN,128,128)
    const float* mlp_b  = (const float*)d_in[5];   // (L,2,NN,128)
    const float* eps    = (const float*)d_in[6];   // (L,2)
    const float* ln_g   = (const float*)d_in[7];   // (L,2,128)
    const float* ln_b   = (const float*)d_in[8];   // (L,2,128)
    const int* edge_ui  = (const int*)d_in[9];     // (2,E): [0]=src user, [1]=dst item
    const int* edge_iu  = (const int*)d_in[10];    // (2,E): [0]=src item, [1]=dst user

    float *xu, *xi, *au, *ai, *t1u, *t2u, *t1i, *t2i;
    cudaGetSymbolAddress((void**)&xu, g_xu);
    cudaGetSymbolAddress((void**)&xi, g_xi);
    cudaGetSymbolAddress((void**)&au, g_agg_u);
    cudaGetSymbolAddress((void**)&ai, g_agg_i);
    cudaGetSymbolAddress((void**)&t1u, g_t1u);
    cudaGetSymbolAddress((void**)&t2u, g_t2u);
    cudaGetSymbolAddress((void**)&t1i, g_t1i);
    cudaGetSymbolAddress((void**)&t2i, g_t2i);

    const int gu = (NU + 127) / 128;   // gemm grid users
    const int gi = (NI + 127) / 128;   // gemm grid items
    const int eblk = (NE * 32 + 255) / 256;
    const int lnu = (NU + 7) / 8;
    const int lni = (NI + 7) / 8;

    // init projection (no relu)
    gemm128<<<gu, 256>>>(x_user, nullptr, nullptr, W_init, b_init, xu, NU, 0);
    gemm128<<<gi, 256>>>(x_item, nullptr, nullptr, W_init + 128 * 128,
                         b_init + 128, xi, NI, 0);

    for (int l = 0; l < NLAY; l++) {
        cudaMemsetAsync(ai, 0, (size_t)NI * CH * sizeof(float), 0);
        cudaMemsetAsync(au, 0, (size_t)NU * CH * sizeof(float), 0);
        // user -> item
        edge_scatter<<<eblk, 256>>>(xu, edge_ui, edge_ui + NE, ai, NE);
        // item -> user
        edge_scatter<<<eblk, 256>>>(xi, edge_iu, edge_iu + NE, au, NE);

        // item MLP: edge type 0
        {
            const float* W0 = mlp_W + (size_t)((l * 2 + 0) * 2 + 0) * 128 * 128;
            const float* W1 = mlp_W + (size_t)((l * 2 + 0) * 2 + 1) * 128 * 128;
            const float* B0 = mlp_b + (size_t)((l * 2 + 0) * 2 + 0) * 128;
            const float* B1 = mlp_b + (size_t)((l * 2 + 0) * 2 + 1) * 128;
            gemm128<<<gi, 256>>>(xi, ai, eps + l * 2 + 0, W0, B0, t1i, NI, 1);
            gemm128<<<gi, 256>>>(t1i, nullptr, nullptr, W1, B1, t2i, NI, 1);
        }
        // user MLP: edge type 1
        {
            const float* W0 = mlp_W + (size_t)((l * 2 + 1) * 2 + 0) * 128 * 128;
            const float* W1 = mlp_W + (size_t)((l * 2 + 1) * 2 + 1) * 128 * 128;
            const float* B0 = mlp_b + (size_t)((l * 2 + 1) * 2 + 0) * 128;
            const float* B1 = mlp_b + (size_t)((l * 2 + 1) * 2 + 1) * 128;
            gemm128<<<gu, 256>>>(xu, au, eps + l * 2 + 1, W0, B0, t1u, NU, 1);
            gemm128<<<gu, 256>>>(t1u, nullptr, nullptr, W1, B1, t2u, NU, 1);
        }

        float* ou = (l == NLAY - 1) ? (float*)d_out : xu;
        float* oi = (l == NLAY - 1) ? (float*)d_out + (size_t)NU * CH : xi;
        // node type 0 = user, 1 = item
        ln_relu<<<lnu, 256>>>(t2u, ln_g + (l * 2 + 0) * 128,
                              ln_b + (l * 2 + 0) * 128, ou, NU);
        ln_relu<<<lni, 256>>>(t2i, ln_g + (l * 2 + 1) * 128,
                              ln_b + (l * 2 + 1) * 128, oi, NI);
    }
}

// round 8
// speedup vs baseline: 1.0106x; 1.0021x over previous
#include <cuda_runtime.h>
#include <cstdint>

#define NU 100000
#define NI 50000
#define CH 128
#define NE 600000
#define NLAY 2

// ---------------- scratch (device globals; no allocation allowed) ------------
__device__ float g_xu[NU * CH];
__device__ float g_xi[NI * CH];
__device__ float g_agg_u[NU * CH];
__device__ float g_agg_i[NI * CH];
__device__ float g_t1u[NU * CH];
__device__ float g_t2u[NU * CH];
__device__ float g_t1i[NI * CH];
__device__ float g_t2i[NI * CH];

// ---------------- packed f32x2 helpers ---------------------------------------
__device__ __forceinline__ unsigned long long pk2(float x, float y) {
    unsigned long long r;
    asm("mov.b64 %0, {%1, %2};" : "=l"(r) : "f"(x), "f"(y));
    return r;
}
__device__ __forceinline__ void fma2(unsigned long long& d, unsigned long long a,
                                     unsigned long long b) {
    asm("fma.rn.f32x2 %0, %1, %2, %0;" : "+l"(d) : "l"(a), "l"(b));
}
__device__ __forceinline__ void upk(unsigned long long v, float& lo, float& hi) {
    asm("mov.b64 {%0, %1}, %2;" : "=f"(lo), "=f"(hi) : "l"(v));
}

// ---------------- GEMM: Y[M,128] = act( (alpha*X + AGG) @ W + bias ) ---------
// BM=BN=128, BK=32, 256 threads, 8x8 register tile, f32x2 packed FMA.
__global__ __launch_bounds__(256) void gemm128(
    const float* __restrict__ X, const float* __restrict__ AGG,
    const float* __restrict__ epsp, const float* __restrict__ W,
    const float* __restrict__ bias, float* __restrict__ Y, int M, int do_relu) {
    __shared__ float As[128][32];
    __shared__ float Bs[32][128];

    const int tid = threadIdx.x;
    const int tx = tid & 15;          // 0..15 -> col tile
    const int ty = tid >> 4;          // 0..15 -> row tile
    const int row0 = blockIdx.x * 128 + ty * 8;

    float alpha = 1.0f;
    if (epsp) alpha = 1.0f + __ldg(epsp);

    unsigned long long acc[8][4];
#pragma unroll
    for (int i = 0; i < 8; i++)
#pragma unroll
        for (int j = 0; j < 4; j++) acc[i][j] = 0ULL;

#pragma unroll 1
    for (int kc = 0; kc < 128; kc += 32) {
        // load A tile (with fused (1+eps)*x + agg), rows of this m-tile
#pragma unroll
        for (int q = 0; q < 4; q++) {
            int f = tid + 256 * q;
            int r = f >> 3, c4 = f & 7;
            int grow = blockIdx.x * 128 + r;
            float4 v = make_float4(0.f, 0.f, 0.f, 0.f);
            if (grow < M) {
                v = *(const float4*)(X + (size_t)grow * CH + kc + c4 * 4);
                if (AGG) {
                    const float4 g =
                        *(const float4*)(AGG + (size_t)grow * CH + kc + c4 * 4);
                    v.x = fmaf(alpha, v.x, g.x);
                    v.y = fmaf(alpha, v.y, g.y);
                    v.z = fmaf(alpha, v.z, g.z);
                    v.w = fmaf(alpha, v.w, g.w);
                }
            }
            *(float4*)&As[r][c4 * 4] = v;
        }
        // load B tile (weights, no guard: K=N=128)
#pragma unroll
        for (int q = 0; q < 4; q++) {
            int f = tid + 256 * q;
            int r = f >> 5, c4 = f & 31;
            *(float4*)&Bs[r][c4 * 4] =
                *(const float4*)(W + (size_t)(kc + r) * CH + c4 * 4);
        }
        __syncthreads();

#pragma unroll
        for (int kk = 0; kk < 32; kk++) {
            unsigned long long pa[8];
#pragma unroll
            for (int i = 0; i < 8; i++) {
                float a = As[ty * 8 + i][kk];
                pa[i] = pk2(a, a);
            }
            const ulonglong2 bb0 = *(const ulonglong2*)&Bs[kk][tx * 8];
            const ulonglong2 bb1 = *(const ulonglong2*)&Bs[kk][tx * 8 + 4];
            unsigned long long bq[4] = {bb0.x, bb0.y, bb1.x, bb1.y};
#pragma unroll
            for (int i = 0; i < 8; i++)
#pragma unroll
                for (int j = 0; j < 4; j++) fma2(acc[i][j], pa[i], bq[j]);
        }
        __syncthreads();
    }

    // epilogue: bias (+ relu) + store
    const float4 bv0 = *(const float4*)(bias + tx * 8);
    const float4 bv1 = *(const float4*)(bias + tx * 8 + 4);
    const float bb[8] = {bv0.x, bv0.y, bv0.z, bv0.w, bv1.x, bv1.y, bv1.z, bv1.w};
#pragma unroll
    for (int i = 0; i < 8; i++) {
        int row = row0 + i;
        if (row < M) {
            float y[8];
#pragma unroll
            for (int j = 0; j < 4; j++) upk(acc[i][j], y[2 * j], y[2 * j + 1]);
#pragma unroll
            for (int j = 0; j < 8; j++) {
                y[j] += bb[j];
                if (do_relu) y[j] = fmaxf(y[j], 0.0f);
            }
            float4 o0 = make_float4(y[0], y[1], y[2], y[3]);
            float4 o1 = make_float4(y[4], y[5], y[6], y[7]);
            float* p = Y + (size_t)row * CH + tx * 8;
            *(float4*)p = o0;
            *(float4*)(p + 4) = o1;
        }
    }
}

// ---------------- edge scatter: agg[dst] += x[src], warp per edge ------------
__global__ void edge_scatter(const float* __restrict__ xsrc,
                             const int* __restrict__ esrc,
                             const int* __restrict__ edst,
                             float* __restrict__ agg, int n_edges) {
    int w = (int)((blockIdx.x * (unsigned)blockDim.x + threadIdx.x) >> 5);
    int lane = threadIdx.x & 31;
    if (w >= n_edges) return;
    int s = __ldg(&esrc[w]);
    int d = __ldg(&edst[w]);
    const float4 v = *(const float4*)(xsrc + (size_t)s * CH + lane * 4);
    float* p = agg + (size_t)d * CH + lane * 4;
    asm volatile("red.global.add.v4.f32 [%0], {%1, %2, %3, %4};"
                 :: "l"(p), "f"(v.x), "f"(v.y), "f"(v.z), "f"(v.w)
                 : "memory");
}

// ---------------- LayerNorm (node mode) + ReLU, warp per node ----------------
__global__ void ln_relu(const float* __restrict__ X, const float* __restrict__ g,
                        const float* __restrict__ b, float* __restrict__ Y,
                        int n) {
    int w = (int)((blockIdx.x * (unsigned)blockDim.x + threadIdx.x) >> 5);
    int lane = threadIdx.x & 31;
    if (w >= n) return;
    const float4 v = *(const float4*)(X + (size_t)w * CH + lane * 4);
    float s = v.x + v.y + v.z + v.w;
#pragma unroll
    for (int o = 16; o > 0; o >>= 1) s += __shfl_xor_sync(0xffffffffu, s, o);
    float m = s * (1.0f / CH);
    float dx0 = v.x - m, dx1 = v.y - m, dx2 = v.z - m, dx3 = v.w - m;
    float ss = dx0 * dx0 + dx1 * dx1 + dx2 * dx2 + dx3 * dx3;
#pragma unroll
    for (int o = 16; o > 0; o >>= 1) ss += __shfl_xor_sync(0xffffffffu, ss, o);
    float inv = rsqrtf(ss * (1.0f / CH) + 1e-5f);
    const float4 gv = *(const float4*)(g + lane * 4);
    const float4 bv = *(const float4*)(b + lane * 4);
    float4 o4;
    o4.x = fmaxf(dx0 * inv * gv.x + bv.x, 0.0f);
    o4.y = fmaxf(dx1 * inv * gv.y + bv.y, 0.0f);
    o4.z = fmaxf(dx2 * inv * gv.z + bv.z, 0.0f);
    o4.w = fmaxf(dx3 * inv * gv.w + bv.w, 0.0f);
    *(float4*)(Y + (size_t)w * CH + lane * 4) = o4;
}

// ---------------- orchestration ---------------------------------------------
extern "C" void kernel_launch(void* const* d_in, const int* in_sizes, int n_in,
                              void* d_out, int out_size) {
    const float* x_user = (const float*)d_in[0];
    const float* x_item = (const float*)d_in[1];
    const float* W_init = (const float*)d_in[2];   // (2,128,128)
    const float* b_init = (const float*)d_in[3];   // (2,128)
    const float* mlp_W  = (const float*)d_in[4];   // (L,2,NN,128,128)
    const float* mlp_b  = (const float*)d_in[5];   // (L,2,NN,128)
    const float* eps    = (const float*)d_in[6];   // (L,2)
    const float* ln_g   = (const float*)d_in[7];   // (L,2,128)
    const float* ln_b   = (const float*)d_in[8];   // (L,2,128)
    const int* edge_ui  = (const int*)d_in[9];     // (2,E): [0]=src user, [1]=dst item
    const int* edge_iu  = (const int*)d_in[10];    // (2,E): [0]=src item, [1]=dst user

    float *xu, *xi, *au, *ai, *t1u, *t2u, *t1i, *t2i;
    cudaGetSymbolAddress((void**)&xu, g_xu);
    cudaGetSymbolAddress((void**)&xi, g_xi);
    cudaGetSymbolAddress((void**)&au, g_agg_u);
    cudaGetSymbolAddress((void**)&ai, g_agg_i);
    cudaGetSymbolAddress((void**)&t1u, g_t1u);
    cudaGetSymbolAddress((void**)&t2u, g_t2u);
    cudaGetSymbolAddress((void**)&t1i, g_t1i);
    cudaGetSymbolAddress((void**)&t2i, g_t2i);

    const int gu = (NU + 127) / 128;   // gemm grid users
    const int gi = (NI + 127) / 128;   // gemm grid items
    const int eblk = (NE * 32 + 255) / 256;
    const int lnu = (NU + 7) / 8;
    const int lni = (NI + 7) / 8;

    // init projection (no relu)
    gemm128<<<gu, 256>>>(x_user, nullptr, nullptr, W_init, b_init, xu, NU, 0);
    gemm128<<<gi, 256>>>(x_item, nullptr, nullptr, W_init + 128 * 128,
                         b_init + 128, xi, NI, 0);

    for (int l = 0; l < NLAY; l++) {
        cudaMemsetAsync(ai, 0, (size_t)NI * CH * sizeof(float), 0);
        cudaMemsetAsync(au, 0, (size_t)NU * CH * sizeof(float), 0);
        // user -> item
        edge_scatter<<<eblk, 256>>>(xu, edge_ui, edge_ui + NE, ai, NE);
        // item -> user
        edge_scatter<<<eblk, 256>>>(xi, edge_iu, edge_iu + NE, au, NE);

        // item MLP: edge type 0
        {
            const float* W0 = mlp_W + (size_t)((l * 2 + 0) * 2 + 0) * 128 * 128;
            const float* W1 = mlp_W + (size_t)((l * 2 + 0) * 2 + 1) * 128 * 128;
            const float* B0 = mlp_b + (size_t)((l * 2 + 0) * 2 + 0) * 128;
            const float* B1 = mlp_b + (size_t)((l * 2 + 0) * 2 + 1) * 128;
            gemm128<<<gi, 256>>>(xi, ai, eps + l * 2 + 0, W0, B0, t1i, NI, 1);
            gemm128<<<gi, 256>>>(t1i, nullptr, nullptr, W1, B1, t2i, NI, 1);
        }
        // user MLP: edge type 1
        {
            const float* W0 = mlp_W + (size_t)((l * 2 + 1) * 2 + 0) * 128 * 128;
            const float* W1 = mlp_W + (size_t)((l * 2 + 1) * 2 + 1) * 128 * 128;
            const float* B0 = mlp_b + (size_t)((l * 2 + 1) * 2 + 0) * 128;
            const float* B1 = mlp_b + (size_t)((l * 2 + 1) * 2 + 1) * 128;
            gemm128<<<gu, 256>>>(xu, au, eps + l * 2 + 1, W0, B0, t1u, NU, 1);
            gemm128<<<gu, 256>>>(t1u, nullptr, nullptr, W1, B1, t2u, NU, 1);
        }

        float* ou = (l == NLAY - 1) ? (float*)d_out : xu;
        float* oi = (l == NLAY - 1) ? (float*)d_out + (size_t)NU * CH : xi;
        // node type 0 = user, 1 = item
        ln_relu<<<lnu, 256>>>(t2u, ln_g + (l * 2 + 0) * 128,
                              ln_b + (l * 2 + 0) * 128, ou, NU);
        ln_relu<<<lni, 256>>>(t2i, ln_g + (l * 2 + 1) * 128,
                              ln_b + (l * 2 + 1) * 128, oi, NI);
    }
}